// round 2
// baseline (speedup 1.0000x reference)
#include <cuda_runtime.h>
#include <math.h>

// Problem constants
#define NS   4096            // tokens S = B*T
#define DM_  768
#define DF_  3072
#define NE   8
#define TOPK 2
#define SLOTS (NS*TOPK)      // 8192
#define TM   128             // row-tile (per-expert padding granularity)
#define CAP  (SLOTS + NE*TM) // 9216 padded rows
#define MAXT (CAP/TM)        // 72 max tiles

// ---------------- scratch (device globals; no allocations allowed) ----------
__device__ int   g_cnt[NE];
__device__ int   g_cur[NE];
__device__ int   g_eid[TOPK*NS];      // expert id per slot, slot = j*S + s
__device__ float g_gw [TOPK*NS];      // combine weight per slot
__device__ int   g_row_tok[CAP];      // token index per grouped row (-1 = pad)
__device__ float g_row_w [CAP];
__device__ int   g_tile_e  [MAXT];
__device__ int   g_tile_row[MAXT];
__device__ int   g_ntiles;
__device__ float g_H[(size_t)CAP * DF_];  // intermediate relu(xW1+b1), ~113MB

// ---------------- 0: reset counters + zero output ---------------------------
__global__ void k_reset(float* __restrict__ out, int n) {
    int i = blockIdx.x * blockDim.x + threadIdx.x;
    if (i < NE) g_cnt[i] = 0;
    for (int j = i; j < n; j += gridDim.x * blockDim.x) out[j] = 0.f;
}

// ---------------- 1: gating (one warp per token) -----------------------------
// top-2 of softmax(logits), renormalized == 2-way softmax over top-2 logits.
__global__ void k_gate(const float* __restrict__ x, const float* __restrict__ Wg) {
    int warp = (blockIdx.x * blockDim.x + threadIdx.x) >> 5;
    int lane = threadIdx.x & 31;
    if (warp >= NS) return;
    const float* xs = x + (size_t)warp * DM_;

    float acc[NE];
#pragma unroll
    for (int e = 0; e < NE; e++) acc[e] = 0.f;
    for (int i = lane; i < DM_; i += 32) {
        float xv = xs[i];
#pragma unroll
        for (int e = 0; e < NE; e++) acc[e] += xv * Wg[i * NE + e];
    }
#pragma unroll
    for (int e = 0; e < NE; e++) {
#pragma unroll
        for (int o = 16; o > 0; o >>= 1)
            acc[e] += __shfl_xor_sync(0xffffffffu, acc[e], o);
    }
    if (lane == 0) {
        int e0 = 0;
#pragma unroll
        for (int e = 1; e < NE; e++) if (acc[e] > acc[e0]) e0 = e;
        int e1 = (e0 == 0) ? 1 : 0;
#pragma unroll
        for (int e = 0; e < NE; e++)
            if (e != e0 && acc[e] > acc[e1]) e1 = e;
        // w0 = exp(l0)/(exp(l0)+exp(l1)); computed stably (l0 >= l1)
        float w1 = 1.f / (1.f + expf(acc[e0] - acc[e1]));
        float w0 = 1.f - w1;
        g_eid[warp]      = e0;  g_gw[warp]      = w0;
        g_eid[NS + warp] = e1;  g_gw[NS + warp] = w1;
        atomicAdd(&g_cnt[e0], 1);
        atomicAdd(&g_cnt[e1], 1);
    }
}

// ---------------- 2: offsets + tile table + pad fill -------------------------
__global__ void k_scan() {
    int t = threadIdx.x;
    for (int i = t; i < CAP; i += blockDim.x) { g_row_tok[i] = -1; g_row_w[i] = 0.f; }
    if (t == 0) {
        int off = 0, nt = 0;
        for (int e = 0; e < NE; e++) {
            g_cur[e] = off;
            int tiles = (g_cnt[e] + TM - 1) / TM;
            for (int k = 0; k < tiles; k++) {
                g_tile_e[nt] = e; g_tile_row[nt] = off + k * TM; nt++;
            }
            off += tiles * TM;
        }
        g_ntiles = nt;
    }
}

// ---------------- 3: scatter slots into per-expert row groups ---------------
__global__ void k_scatter() {
    int i = blockIdx.x * blockDim.x + threadIdx.x;
    if (i >= SLOTS) return;
    int e = g_eid[i];
    int pos = atomicAdd(&g_cur[e], 1);
    g_row_tok[pos] = i % NS;       // slot = j*S + s  ->  token s
    g_row_w[pos]   = g_gw[i];
}

// ---------------- 4: FFN layer 1: H = relu(Xg @ W1[e] + b1[e]) --------------
// 128x128x8 tiling, 256 threads, 8x8 accum per thread.
__global__ void __launch_bounds__(256, 2)
k_ffn1(const float* __restrict__ x, const float* __restrict__ W1,
       const float* __restrict__ b1) {
    int t = blockIdx.x;
    if (t >= g_ntiles) return;
    int e    = g_tile_e[t];
    int row0 = g_tile_row[t];
    int n0   = blockIdx.y * 128;
    const float* W = W1 + (size_t)e * DM_ * DF_;

    __shared__ float As[8][128];
    __shared__ float Bs[8][128];

    int tid  = threadIdx.x;
    int arow = tid >> 1, aseg = tid & 1;          // A: 2 float4 per row
    int atok = g_row_tok[row0 + arow];
    const float* aptr = (atok >= 0) ? x + (size_t)atok * DM_ + aseg * 4 : nullptr;
    int brow = tid >> 5, bcol = (tid & 31) * 4;   // B: 8 rows x 128 cols
    int tx = tid & 15, ty = tid >> 4;

    float acc[8][8];
#pragma unroll
    for (int i = 0; i < 8; i++)
#pragma unroll
        for (int j = 0; j < 8; j++) acc[i][j] = 0.f;

    for (int k0 = 0; k0 < DM_; k0 += 8) {
        float4 av = aptr ? *(const float4*)(aptr + k0) : make_float4(0, 0, 0, 0);
        float4 bv = *(const float4*)(W + (size_t)(k0 + brow) * DF_ + n0 + bcol);
        __syncthreads();
        As[aseg * 4 + 0][arow] = av.x;
        As[aseg * 4 + 1][arow] = av.y;
        As[aseg * 4 + 2][arow] = av.z;
        As[aseg * 4 + 3][arow] = av.w;
        *(float4*)&Bs[brow][bcol] = bv;
        __syncthreads();
#pragma unroll
        for (int k = 0; k < 8; k++) {
            float a[8], b[8];
            *(float4*)(a)     = *(float4*)&As[k][ty * 8];
            *(float4*)(a + 4) = *(float4*)&As[k][ty * 8 + 4];
            *(float4*)(b)     = *(float4*)&Bs[k][tx * 8];
            *(float4*)(b + 4) = *(float4*)&Bs[k][tx * 8 + 4];
#pragma unroll
            for (int i = 0; i < 8; i++)
#pragma unroll
                for (int j = 0; j < 8; j++) acc[i][j] += a[i] * b[j];
        }
    }

    // hoist bias slice into registers
    float bb[8];
#pragma unroll
    for (int j = 0; j < 8; j++) bb[j] = b1[(size_t)e * DF_ + n0 + tx * 8 + j];

#pragma unroll
    for (int i = 0; i < 8; i++) {
        int r = row0 + ty * 8 + i;
        float* hp = g_H + (size_t)r * DF_ + n0 + tx * 8;
#pragma unroll
        for (int j4 = 0; j4 < 8; j4 += 4) {
            float4 v;
            v.x = fmaxf(acc[i][j4 + 0] + bb[j4 + 0], 0.f);
            v.y = fmaxf(acc[i][j4 + 1] + bb[j4 + 1], 0.f);
            v.z = fmaxf(acc[i][j4 + 2] + bb[j4 + 2], 0.f);
            v.w = fmaxf(acc[i][j4 + 3] + bb[j4 + 3], 0.f);
            *(float4*)(hp + j4) = v;
        }
    }
}

// ---------------- 5: FFN layer 2 + weighted scatter-combine ------------------
// out[token] += w * (H @ W2[e] + b2[e]).  Exactly 2 commutative fp adds per
// output element (token has 2 distinct experts) -> bitwise deterministic.
__global__ void __launch_bounds__(256, 2)
k_ffn2(float* __restrict__ out, const float* __restrict__ W2,
       const float* __restrict__ b2) {
    int t = blockIdx.x;
    if (t >= g_ntiles) return;
    int e    = g_tile_e[t];
    int row0 = g_tile_row[t];
    int n0   = blockIdx.y * 128;
    const float* W = W2 + (size_t)e * DF_ * DM_;

    __shared__ float As[8][128];
    __shared__ float Bs[8][128];

    int tid  = threadIdx.x;
    int arow = tid >> 1, aseg = tid & 1;
    const float* aptr = g_H + (size_t)(row0 + arow) * DF_ + aseg * 4;
    int brow = tid >> 5, bcol = (tid & 31) * 4;
    int tx = tid & 15, ty = tid >> 4;

    float acc[8][8];
#pragma unroll
    for (int i = 0; i < 8; i++)
#pragma unroll
        for (int j = 0; j < 8; j++) acc[i][j] = 0.f;

    for (int k0 = 0; k0 < DF_; k0 += 8) {
        float4 av = *(const float4*)(aptr + k0);
        float4 bv = *(const float4*)(W + (size_t)(k0 + brow) * DM_ + n0 + bcol);
        __syncthreads();
        As[aseg * 4 + 0][arow] = av.x;
        As[aseg * 4 + 1][arow] = av.y;
        As[aseg * 4 + 2][arow] = av.z;
        As[aseg * 4 + 3][arow] = av.w;
        *(float4*)&Bs[brow][bcol] = bv;
        __syncthreads();
#pragma unroll
        for (int k = 0; k < 8; k++) {
            float a[8], b[8];
            *(float4*)(a)     = *(float4*)&As[k][ty * 8];
            *(float4*)(a + 4) = *(float4*)&As[k][ty * 8 + 4];
            *(float4*)(b)     = *(float4*)&Bs[k][tx * 8];
            *(float4*)(b + 4) = *(float4*)&Bs[k][tx * 8 + 4];
#pragma unroll
            for (int i = 0; i < 8; i++)
#pragma unroll
                for (int j = 0; j < 8; j++) acc[i][j] += a[i] * b[j];
        }
    }

    // hoist bias slice into registers
    float bb[8];
#pragma unroll
    for (int j = 0; j < 8; j++) bb[j] = b2[(size_t)e * DM_ + n0 + tx * 8 + j];

#pragma unroll
    for (int i = 0; i < 8; i++) {
        int r = row0 + ty * 8 + i;
        int tok = g_row_tok[r];
        if (tok < 0) continue;
        float w = g_row_w[r];
        float* op = out + (size_t)tok * DM_ + n0 + tx * 8;
#pragma unroll
        for (int j = 0; j < 8; j++) {
            float v = acc[i][j] + bb[j];
            atomicAdd(op + j, w * v);
        }
    }
}

// ---------------- launch -----------------------------------------------------
extern "C" void kernel_launch(void* const* d_in, const int* in_sizes, int n_in,
                              void* d_out, int out_size) {
    const float* x  = (const float*)d_in[0];
    const float* Wg = (const float*)d_in[1];
    const float* W1 = (const float*)d_in[2];
    const float* b1 = (const float*)d_in[3];
    const float* W2 = (const float*)d_in[4];
    const float* b2 = (const float*)d_in[5];
    float* out = (float*)d_out;

    k_reset<<<256, 256>>>(out, out_size);
    k_gate<<<(NS * 32 + 255) / 256, 256>>>(x, Wg);
    k_scan<<<1, 256>>>();
    k_scatter<<<(SLOTS + 255) / 256, 256>>>();
    k_ffn1<<<dim3(MAXT, DF_ / 128), 256>>>(x, W1, b1);
    k_ffn2<<<dim3(MAXT, DM_ / 128), 256>>>(out, W2, b2);
}

// round 10
// speedup vs baseline: 1.6303x; 1.6303x over previous
#include <cuda_runtime.h>
#include <cstdint>
#include <math.h>

// ---------------- problem constants -----------------------------------------
#define NS   4096
#define DM_  768
#define DF_  3072
#define NE   8
#define TOPK 2
#define SLOTS (NS*TOPK)
#define TM   128
#define CAP  (SLOTS + NE*TM)    // 9216 padded rows
#define MAXT (CAP/TM)           // 72

#define ASTR 36                 // A smem row stride (floats): (4r+k)%32 distinct
#define BSTR 136                // B smem row stride (floats): (8k+n)%32 distinct

// ---------------- device scratch (no allocations allowed) -------------------
__device__ int   g_cnt[NE];
__device__ int   g_cur[NE];
__device__ int   g_eid[SLOTS];
__device__ float g_gw [SLOTS];
__device__ int   g_row_tok[CAP];
__device__ float g_row_w [CAP];
__device__ int   g_tile_e  [MAXT];
__device__ int   g_tile_row[MAXT];
__device__ int   g_ntiles;
__device__ float g_H[(size_t)CAP * DF_];   // 113 MB fp32 intermediate

// ---------------- helpers -----------------------------------------------------
__device__ __forceinline__ uint32_t f2tf32(float x) {
    uint32_t r; asm("cvt.rna.tf32.f32 %0, %1;" : "=r"(r) : "f"(x)); return r;
}

__device__ __forceinline__ void mma_tf32(float& c0, float& c1, float& c2, float& c3,
                                         uint32_t a0, uint32_t a1, uint32_t a2, uint32_t a3,
                                         uint32_t b0, uint32_t b1) {
    asm volatile(
        "mma.sync.aligned.m16n8k8.row.col.f32.tf32.tf32.f32 "
        "{%0,%1,%2,%3}, {%4,%5,%6,%7}, {%8,%9}, {%0,%1,%2,%3};"
        : "+f"(c0), "+f"(c1), "+f"(c2), "+f"(c3)
        : "r"(a0), "r"(a1), "r"(a2), "r"(a3), "r"(b0), "r"(b1));
}

// ---------------- 0: reset + zero output -------------------------------------
__global__ void k_reset(float* __restrict__ out, int n) {
    int i = blockIdx.x * blockDim.x + threadIdx.x;
    if (i < NE) g_cnt[i] = 0;
    for (int j = i; j < n; j += gridDim.x * blockDim.x) out[j] = 0.f;
}

// ---------------- 1: gating (one warp per token, pure fp32) ------------------
__global__ void k_gate(const float* __restrict__ x, const float* __restrict__ Wg) {
    int warp = (blockIdx.x * blockDim.x + threadIdx.x) >> 5;
    int lane = threadIdx.x & 31;
    if (warp >= NS) return;
    const float* xs = x + (size_t)warp * DM_;
    float acc[NE];
#pragma unroll
    for (int e = 0; e < NE; e++) acc[e] = 0.f;
    for (int i = lane; i < DM_; i += 32) {
        float xv = xs[i];
#pragma unroll
        for (int e = 0; e < NE; e++) acc[e] += xv * Wg[i * NE + e];
    }
#pragma unroll
    for (int e = 0; e < NE; e++)
#pragma unroll
        for (int o = 16; o > 0; o >>= 1)
            acc[e] += __shfl_xor_sync(0xffffffffu, acc[e], o);
    if (lane == 0) {
        int e0 = 0;
#pragma unroll
        for (int e = 1; e < NE; e++) if (acc[e] > acc[e0]) e0 = e;
        int e1 = (e0 == 0) ? 1 : 0;
#pragma unroll
        for (int e = 0; e < NE; e++)
            if (e != e0 && acc[e] > acc[e1]) e1 = e;
        float w1 = 1.f / (1.f + expf(acc[e0] - acc[e1]));
        float w0 = 1.f - w1;
        g_eid[warp]      = e0;  g_gw[warp]      = w0;
        g_eid[NS + warp] = e1;  g_gw[NS + warp] = w1;
        atomicAdd(&g_cnt[e0], 1);
        atomicAdd(&g_cnt[e1], 1);
    }
}

// ---------------- 2: offsets + tile table ------------------------------------
__global__ void k_scan() {
    int t = threadIdx.x;
    for (int i = t; i < CAP; i += blockDim.x) { g_row_tok[i] = -1; g_row_w[i] = 0.f; }
    if (t == 0) {
        int off = 0, nt = 0;
        for (int e = 0; e < NE; e++) {
            g_cur[e] = off;
            int tiles = (g_cnt[e] + TM - 1) / TM;
            for (int k = 0; k < tiles; k++) {
                g_tile_e[nt] = e; g_tile_row[nt] = off + k * TM; nt++;
            }
            off += tiles * TM;
        }
        g_ntiles = nt;
    }
}

// ---------------- 3: scatter --------------------------------------------------
__global__ void k_scatter() {
    int i = blockIdx.x * blockDim.x + threadIdx.x;
    if (i >= SLOTS) return;
    int e = g_eid[i];
    int pos = atomicAdd(&g_cur[e], 1);
    g_row_tok[pos] = i % NS;
    g_row_w[pos]   = g_gw[i];
}

// ---------------- 4: warp-MMA grouped GEMM (prefetch-pipelined) --------------
// Block: 256 thr = 8 warps (4m x 2n).  Tile 128m x 128n x k32.
// FFN2=false: H = relu(Xg @ W1[e] + b1[e])  (H fp32)
// FFN2=true : out[tok] += w * (H @ W2[e] + b2[e])  (atomic; 2 adds/elem)
template<bool FFN2>
__global__ void __launch_bounds__(256, 2) k_ffn_mma(
    const float* __restrict__ x, const float* __restrict__ W1or2,
    const float* __restrict__ bias, float* __restrict__ out)
{
    int t = blockIdx.x;
    if (t >= g_ntiles) return;

    __shared__ uint32_t As[128 * ASTR];   // tf32 bits, [m][k] stride ASTR
    __shared__ uint32_t Bs[32 * BSTR];    // tf32 bits, [k][n] stride BSTR
    __shared__ int   stok[TM];
    __shared__ float sw  [TM];

    const int KDIM = FFN2 ? DF_ : DM_;
    const int NDIM = FFN2 ? DM_ : DF_;
    int e    = g_tile_e[t];
    int row0 = g_tile_row[t];
    int n0   = blockIdx.y * 128;
    int tid  = threadIdx.x;
    int wid  = tid >> 5, lane = tid & 31;
    int gid  = lane >> 2, tig = lane & 3;   // mma group id / thread-in-group
    int wm   = wid >> 1,  wn  = wid & 1;    // warp tile coords: 4m x 2n
    int m0w  = wm * 32,   n0w = wn * 64;

    if (tid < TM) {
        stok[tid] = g_row_tok[row0 + tid];
        sw[tid]   = g_row_w [row0 + tid];
    }
    __syncthreads();

    const float* W = W1or2 + (size_t)e * DM_ * DF_;

    // global-load mapping
    int arow = tid >> 1, ahalf = tid & 1;          // A: 128 rows x 2 half-rows(16f)
    int brow = tid >> 3, bseg  = tid & 7;          // B: 32 rows x 8 segs(16f)
    const float* aptr = nullptr;
    if (FFN2) {
        aptr = g_H + (size_t)(row0 + arow) * DF_ + ahalf * 16;
    } else {
        int tok = stok[arow];
        if (tok >= 0) aptr = x + (size_t)tok * DM_ + ahalf * 16;
    }
    const float* bptr = W + (size_t)brow * NDIM + n0 + bseg * 16;

    float acc[2][8][4];
#pragma unroll
    for (int mf = 0; mf < 2; mf++)
#pragma unroll
        for (int nf = 0; nf < 8; nf++)
#pragma unroll
            for (int q = 0; q < 4; q++) acc[mf][nf][q] = 0.f;

    const int NC = KDIM / 32;
    uint32_t areg[16], breg[16];

    // ---- preload chunk 0 into regs (tf32-rounded) ----
    {
#pragma unroll
        for (int q = 0; q < 4; q++) {
            float4 v = aptr ? *(const float4*)(aptr + q * 4)
                            : make_float4(0.f, 0.f, 0.f, 0.f);
            areg[q*4+0] = f2tf32(v.x); areg[q*4+1] = f2tf32(v.y);
            areg[q*4+2] = f2tf32(v.z); areg[q*4+3] = f2tf32(v.w);
        }
#pragma unroll
        for (int q = 0; q < 4; q++) {
            float4 v = *(const float4*)(bptr + q * 4);
            breg[q*4+0] = f2tf32(v.x); breg[q*4+1] = f2tf32(v.y);
            breg[q*4+2] = f2tf32(v.z); breg[q*4+3] = f2tf32(v.w);
        }
    }

    for (int c = 0; c < NC; c++) {
        __syncthreads();   // previous chunk's MMAs done before smem overwrite
#pragma unroll
        for (int q = 0; q < 4; q++)
            *(uint4*)&As[arow * ASTR + ahalf * 16 + q * 4] = *(uint4*)&areg[q*4];
#pragma unroll
        for (int q = 0; q < 4; q++)
            *(uint4*)&Bs[brow * BSTR + bseg * 16 + q * 4] = *(uint4*)&breg[q*4];
        __syncthreads();

        // ---- prefetch chunk c+1 (LDG issues before the MMA block) ----
        if (c + 1 < NC) {
            int k0n = (c + 1) * 32;
#pragma unroll
            for (int q = 0; q < 4; q++) {
                float4 v = aptr ? *(const float4*)(aptr + k0n + q * 4)
                                : make_float4(0.f, 0.f, 0.f, 0.f);
                areg[q*4+0] = f2tf32(v.x); areg[q*4+1] = f2tf32(v.y);
                areg[q*4+2] = f2tf32(v.z); areg[q*4+3] = f2tf32(v.w);
            }
#pragma unroll
            for (int q = 0; q < 4; q++) {
                float4 v = *(const float4*)(bptr + (size_t)k0n * NDIM + q * 4);
                breg[q*4+0] = f2tf32(v.x); breg[q*4+1] = f2tf32(v.y);
                breg[q*4+2] = f2tf32(v.z); breg[q*4+3] = f2tf32(v.w);
            }
        }

        // ---- compute 4 k-slices of 8 on chunk c ----
#pragma unroll
        for (int ks = 0; ks < 32; ks += 8) {
            uint32_t a[2][4];
#pragma unroll
            for (int mf = 0; mf < 2; mf++) {
                int mr = m0w + mf * 16 + gid;
                a[mf][0] = As[mr * ASTR + ks + tig];
                a[mf][1] = As[(mr + 8) * ASTR + ks + tig];
                a[mf][2] = As[mr * ASTR + ks + tig + 4];
                a[mf][3] = As[(mr + 8) * ASTR + ks + tig + 4];
            }
#pragma unroll
            for (int nf = 0; nf < 8; nf++) {
                int nc = n0w + nf * 8 + gid;
                uint32_t b0 = Bs[(ks + tig) * BSTR + nc];
                uint32_t b1 = Bs[(ks + tig + 4) * BSTR + nc];
#pragma unroll
                for (int mf = 0; mf < 2; mf++)
                    mma_tf32(acc[mf][nf][0], acc[mf][nf][1],
                             acc[mf][nf][2], acc[mf][nf][3],
                             a[mf][0], a[mf][1], a[mf][2], a[mf][3], b0, b1);
            }
        }
    }

    // epilogue
    const float* bb = bias + (size_t)e * NDIM + n0;
#pragma unroll
    for (int mf = 0; mf < 2; mf++) {
        int rbase = m0w + mf * 16 + gid;
#pragma unroll
        for (int half = 0; half < 2; half++) {       // rows rbase, rbase+8
            int r = rbase + half * 8;
            if (FFN2) {
                int tok = stok[r];
                if (tok < 0) continue;
                float w = sw[r];
                float* op = out + (size_t)tok * DM_ + n0;
#pragma unroll
                for (int nf = 0; nf < 8; nf++) {
                    int cc = wn * 64 + nf * 8 + tig * 2;
                    atomicAdd(op + cc,     w * (acc[mf][nf][half*2+0] + bb[cc]));
                    atomicAdd(op + cc + 1, w * (acc[mf][nf][half*2+1] + bb[cc+1]));
                }
            } else {
                float* hp = g_H + (size_t)(row0 + r) * DF_ + n0;
#pragma unroll
                for (int nf = 0; nf < 8; nf++) {
                    int cc = wn * 64 + nf * 8 + tig * 2;
                    float2 v;
                    v.x = fmaxf(acc[mf][nf][half*2+0] + bb[cc],     0.f);
                    v.y = fmaxf(acc[mf][nf][half*2+1] + bb[cc + 1], 0.f);
                    *(float2*)(hp + cc) = v;
                }
            }
        }
    }
}

// ---------------- launch -----------------------------------------------------
extern "C" void kernel_launch(void* const* d_in, const int* in_sizes, int n_in,
                              void* d_out, int out_size) {
    const float* x  = (const float*)d_in[0];
    const float* Wg = (const float*)d_in[1];
    const float* W1 = (const float*)d_in[2];
    const float* b1 = (const float*)d_in[3];
    const float* W2 = (const float*)d_in[4];
    const float* b2 = (const float*)d_in[5];
    float* out = (float*)d_out;

    k_reset<<<256, 256>>>(out, out_size);
    k_gate<<<(NS * 32 + 255) / 256, 256>>>(x, Wg);
    k_scan<<<1, 256>>>();
    k_scatter<<<(SLOTS + 255) / 256, 256>>>();
    k_ffn_mma<false><<<dim3(MAXT, DF_ / 128), 256>>>(x, W1, b1, nullptr);
    k_ffn_mma<true ><<<dim3(MAXT, DM_ / 128), 256>>>(x, W2, b2, out);
}

// round 13
// speedup vs baseline: 2.1851x; 1.3403x over previous
#include <cuda_runtime.h>
#include <cstdint>
#include <math.h>

// ---------------- problem constants -----------------------------------------
#define NS   4096
#define DM_  768
#define DF_  3072
#define NE   8
#define TOPK 2
#define SLOTS (NS*TOPK)
#define TM   128
#define CAP  (SLOTS + NE*TM)    // 9216 padded rows
#define MAXT (CAP/TM)           // 72
#define TM2  64
#define MAXT2 (CAP/TM2)         // 144

#define ASTR 36                 // A smem row stride (floats)
#define BSTR 136                // B smem row stride (floats)

// ---------------- device scratch (no allocations allowed) -------------------
__device__ int   g_cnt[NE];
__device__ int   g_cur[NE];
__device__ int   g_eid[SLOTS];
__device__ float g_gw [SLOTS];
__device__ int   g_row_tok[CAP];
__device__ float g_row_w [CAP];
__device__ int   g_tile_e  [MAXT];
__device__ int   g_tile_row[MAXT];
__device__ int   g_ntiles;
__device__ int   g_tile2_e  [MAXT2];
__device__ int   g_tile2_row[MAXT2];
__device__ int   g_ntiles2;
__device__ float g_H[(size_t)CAP * DF_];   // 113 MB fp32 intermediate

// ---------------- helpers -----------------------------------------------------
__device__ __forceinline__ uint32_t f2tf32(float x) {
    uint32_t r; asm("cvt.rna.tf32.f32 %0, %1;" : "=r"(r) : "f"(x)); return r;
}

__device__ __forceinline__ void mma_tf32(float& c0, float& c1, float& c2, float& c3,
                                         uint32_t a0, uint32_t a1, uint32_t a2, uint32_t a3,
                                         uint32_t b0, uint32_t b1) {
    asm volatile(
        "mma.sync.aligned.m16n8k8.row.col.f32.tf32.tf32.f32 "
        "{%0,%1,%2,%3}, {%4,%5,%6,%7}, {%8,%9}, {%0,%1,%2,%3};"
        : "+f"(c0), "+f"(c1), "+f"(c2), "+f"(c3)
        : "r"(a0), "r"(a1), "r"(a2), "r"(a3), "r"(b0), "r"(b1));
}

__device__ __forceinline__ uint4 cvt4(float4 v) {
    uint4 u;
    u.x = f2tf32(v.x); u.y = f2tf32(v.y); u.z = f2tf32(v.z); u.w = f2tf32(v.w);
    return u;
}

// ---------------- 0: reset + zero output -------------------------------------
__global__ void k_reset(float* __restrict__ out, int n) {
    int i = blockIdx.x * blockDim.x + threadIdx.x;
    if (i < NE) g_cnt[i] = 0;
    for (int j = i; j < n; j += gridDim.x * blockDim.x) out[j] = 0.f;
}

// ---------------- 1: gating (one warp per token, pure fp32) ------------------
__global__ void k_gate(const float* __restrict__ x, const float* __restrict__ Wg) {
    int warp = (blockIdx.x * blockDim.x + threadIdx.x) >> 5;
    int lane = threadIdx.x & 31;
    if (warp >= NS) return;
    const float* xs = x + (size_t)warp * DM_;
    float acc[NE];
#pragma unroll
    for (int e = 0; e < NE; e++) acc[e] = 0.f;
    for (int i = lane; i < DM_; i += 32) {
        float xv = xs[i];
#pragma unroll
        for (int e = 0; e < NE; e++) acc[e] += xv * Wg[i * NE + e];
    }
#pragma unroll
    for (int e = 0; e < NE; e++)
#pragma unroll
        for (int o = 16; o > 0; o >>= 1)
            acc[e] += __shfl_xor_sync(0xffffffffu, acc[e], o);
    if (lane == 0) {
        int e0 = 0;
#pragma unroll
        for (int e = 1; e < NE; e++) if (acc[e] > acc[e0]) e0 = e;
        int e1 = (e0 == 0) ? 1 : 0;
#pragma unroll
        for (int e = 0; e < NE; e++)
            if (e != e0 && acc[e] > acc[e1]) e1 = e;
        float w1 = 1.f / (1.f + expf(acc[e0] - acc[e1]));
        float w0 = 1.f - w1;
        g_eid[warp]      = e0;  g_gw[warp]      = w0;
        g_eid[NS + warp] = e1;  g_gw[NS + warp] = w1;
        atomicAdd(&g_cnt[e0], 1);
        atomicAdd(&g_cnt[e1], 1);
    }
}

// ---------------- 2: offsets + tile tables (128-row and 64-row) --------------
__global__ void k_scan() {
    int t = threadIdx.x;
    for (int i = t; i < CAP; i += blockDim.x) { g_row_tok[i] = -1; g_row_w[i] = 0.f; }
    if (t == 0) {
        int off = 0, nt = 0, nt2 = 0;
        for (int e = 0; e < NE; e++) {
            g_cur[e] = off;
            int cnt = g_cnt[e];
            int tiles = (cnt + TM - 1) / TM;
            for (int k = 0; k < tiles; k++) {
                g_tile_e[nt] = e; g_tile_row[nt] = off + k * TM; nt++;
            }
            int tiles2 = (cnt + TM2 - 1) / TM2;
            for (int k = 0; k < tiles2; k++) {
                g_tile2_e[nt2] = e; g_tile2_row[nt2] = off + k * TM2; nt2++;
            }
            off += tiles * TM;
        }
        g_ntiles = nt;
        g_ntiles2 = nt2;
    }
}

// ---------------- 3: scatter --------------------------------------------------
__global__ void k_scatter() {
    int i = blockIdx.x * blockDim.x + threadIdx.x;
    if (i >= SLOTS) return;
    int e = g_eid[i];
    int pos = atomicAdd(&g_cur[e], 1);
    g_row_tok[pos] = i % NS;
    g_row_w[pos]   = g_gw[i];
}

// ---------------- 4: FFN1  H = relu(Xg @ W1[e] + b1[e]) ----------------------
// Tile 128m x 128n x k32.  8 warps (4m x 2n), warp tile 32x64.
// Raw-float staging; tf32 cvt at STS time -> LDG latency hidden by MMA block.
__global__ void __launch_bounds__(256, 2) k_ffn1(
    const float* __restrict__ x, const float* __restrict__ W1,
    const float* __restrict__ bias)
{
    int t = blockIdx.x;
    if (t >= g_ntiles) return;

    __shared__ uint32_t As[128 * ASTR];
    __shared__ uint32_t Bs[32 * BSTR];
    __shared__ int   stok[TM];

    int e    = g_tile_e[t];
    int row0 = g_tile_row[t];
    int n0   = blockIdx.y * 128;
    int tid  = threadIdx.x;
    int wid  = tid >> 5, lane = tid & 31;
    int gid  = lane >> 2, tig = lane & 3;
    int wm   = wid >> 1,  wn  = wid & 1;
    int m0w  = wm * 32,   n0w = wn * 64;

    if (tid < TM) stok[tid] = g_row_tok[row0 + tid];
    __syncthreads();

    const float* W = W1 + (size_t)e * DM_ * DF_;

    int arow = tid >> 1, ahalf = tid & 1;          // A: 128 rows x 2 halves(16f)
    int brow = tid >> 3, bseg  = tid & 7;          // B: 32 rows x 8 segs(16f)
    const float* aptr = nullptr;
    {
        int tok = stok[arow];
        if (tok >= 0) aptr = x + (size_t)tok * DM_ + ahalf * 16;
    }
    const float* bptr = W + (size_t)brow * DF_ + n0 + bseg * 16;

    float acc[2][8][4];
#pragma unroll
    for (int mf = 0; mf < 2; mf++)
#pragma unroll
        for (int nf = 0; nf < 8; nf++)
#pragma unroll
            for (int q = 0; q < 4; q++) acc[mf][nf][q] = 0.f;

    const int NC = DM_ / 32;
    float4 fa[4], fb[4];

    // preload chunk 0 (raw floats)
#pragma unroll
    for (int q = 0; q < 4; q++)
        fa[q] = aptr ? *(const float4*)(aptr + q * 4) : make_float4(0.f,0.f,0.f,0.f);
#pragma unroll
    for (int q = 0; q < 4; q++)
        fb[q] = *(const float4*)(bptr + q * 4);

    for (int c = 0; c < NC; c++) {
        __syncthreads();
#pragma unroll
        for (int q = 0; q < 4; q++)
            *(uint4*)&As[arow * ASTR + ahalf * 16 + q * 4] = cvt4(fa[q]);
#pragma unroll
        for (int q = 0; q < 4; q++)
            *(uint4*)&Bs[brow * BSTR + bseg * 16 + q * 4] = cvt4(fb[q]);
        __syncthreads();

        if (c + 1 < NC) {           // raw prefetch: consumed only next iteration
            int k0n = (c + 1) * 32;
#pragma unroll
            for (int q = 0; q < 4; q++)
                fa[q] = aptr ? *(const float4*)(aptr + k0n + q * 4)
                             : make_float4(0.f,0.f,0.f,0.f);
#pragma unroll
            for (int q = 0; q < 4; q++)
                fb[q] = *(const float4*)(bptr + (size_t)k0n * DF_ + q * 4);
        }

#pragma unroll
        for (int ks = 0; ks < 32; ks += 8) {
            uint32_t a[2][4];
#pragma unroll
            for (int mf = 0; mf < 2; mf++) {
                int mr = m0w + mf * 16 + gid;
                a[mf][0] = As[mr * ASTR + ks + tig];
                a[mf][1] = As[(mr + 8) * ASTR + ks + tig];
                a[mf][2] = As[mr * ASTR + ks + tig + 4];
                a[mf][3] = As[(mr + 8) * ASTR + ks + tig + 4];
            }
#pragma unroll
            for (int nf = 0; nf < 8; nf++) {
                int nc = n0w + nf * 8 + gid;
                uint32_t b0 = Bs[(ks + tig) * BSTR + nc];
                uint32_t b1 = Bs[(ks + tig + 4) * BSTR + nc];
#pragma unroll
                for (int mf = 0; mf < 2; mf++)
                    mma_tf32(acc[mf][nf][0], acc[mf][nf][1],
                             acc[mf][nf][2], acc[mf][nf][3],
                             a[mf][0], a[mf][1], a[mf][2], a[mf][3], b0, b1);
            }
        }
    }

    const float* bb = bias + (size_t)e * DF_ + n0;
#pragma unroll
    for (int mf = 0; mf < 2; mf++) {
        int rbase = m0w + mf * 16 + gid;
#pragma unroll
        for (int half = 0; half < 2; half++) {
            int r = rbase + half * 8;
            float* hp = g_H + (size_t)(row0 + r) * DF_ + n0;
#pragma unroll
            for (int nf = 0; nf < 8; nf++) {
                int cc = wn * 64 + nf * 8 + tig * 2;
                float2 v;
                v.x = fmaxf(acc[mf][nf][half*2+0] + bb[cc],     0.f);
                v.y = fmaxf(acc[mf][nf][half*2+1] + bb[cc + 1], 0.f);
                *(float2*)(hp + cc) = v;
            }
        }
    }
}

// ---------------- 5: FFN2  out[tok] += w * (H @ W2[e] + b2[e]) ---------------
// Tile 64m x 128n x k32 (finer m => 864 blocks, no 1.46-wave tail).
// 8 warps (2m x 4n), warp tile 32x32.  K unsplit => exactly 2 adds per output.
__global__ void __launch_bounds__(256, 2) k_ffn2(
    const float* __restrict__ W2, const float* __restrict__ bias,
    float* __restrict__ out)
{
    int t = blockIdx.x;
    if (t >= g_ntiles2) return;

    __shared__ uint32_t As[TM2 * ASTR];
    __shared__ uint32_t Bs[32 * BSTR];
    __shared__ int   stok[TM2];
    __shared__ float sw  [TM2];

    int e    = g_tile2_e[t];
    int row0 = g_tile2_row[t];
    int n0   = blockIdx.y * 128;
    int tid  = threadIdx.x;
    int wid  = tid >> 5, lane = tid & 31;
    int gid  = lane >> 2, tig = lane & 3;
    int wm   = wid >> 2,  wn  = wid & 3;     // 2m x 4n
    int m0w  = wm * 32,   n0w = wn * 32;

    if (tid < TM2) {
        stok[tid] = g_row_tok[row0 + tid];
        sw[tid]   = g_row_w [row0 + tid];
    }
    __syncthreads();

    const float* W = W2 + (size_t)e * DF_ * DM_;

    int arow = tid >> 2, aseg = tid & 3;     // A: 64 rows x 4 segs(8f)
    int brow = tid >> 3, bseg = tid & 7;     // B: 32 rows x 8 segs(16f)
    const float* aptr = g_H + (size_t)(row0 + arow) * DF_ + aseg * 8;
    const float* bptr = W + (size_t)brow * DM_ + n0 + bseg * 16;

    float acc[2][4][4];
#pragma unroll
    for (int mf = 0; mf < 2; mf++)
#pragma unroll
        for (int nf = 0; nf < 4; nf++)
#pragma unroll
            for (int q = 0; q < 4; q++) acc[mf][nf][q] = 0.f;

    const int NC = DF_ / 32;
    float4 fa[2], fb[4];

#pragma unroll
    for (int q = 0; q < 2; q++) fa[q] = *(const float4*)(aptr + q * 4);
#pragma unroll
    for (int q = 0; q < 4; q++) fb[q] = *(const float4*)(bptr + q * 4);

    for (int c = 0; c < NC; c++) {
        __syncthreads();
#pragma unroll
        for (int q = 0; q < 2; q++)
            *(uint4*)&As[arow * ASTR + aseg * 8 + q * 4] = cvt4(fa[q]);
#pragma unroll
        for (int q = 0; q < 4; q++)
            *(uint4*)&Bs[brow * BSTR + bseg * 16 + q * 4] = cvt4(fb[q]);
        __syncthreads();

        if (c + 1 < NC) {
            int k0n = (c + 1) * 32;
#pragma unroll
            for (int q = 0; q < 2; q++)
                fa[q] = *(const float4*)(aptr + k0n + q * 4);
#pragma unroll
            for (int q = 0; q < 4; q++)
                fb[q] = *(const float4*)(bptr + (size_t)k0n * DM_ + q * 4);
        }

#pragma unroll
        for (int ks = 0; ks < 32; ks += 8) {
            uint32_t a[2][4];
#pragma unroll
            for (int mf = 0; mf < 2; mf++) {
                int mr = m0w + mf * 16 + gid;
                a[mf][0] = As[mr * ASTR + ks + tig];
                a[mf][1] = As[(mr + 8) * ASTR + ks + tig];
                a[mf][2] = As[mr * ASTR + ks + tig + 4];
                a[mf][3] = As[(mr + 8) * ASTR + ks + tig + 4];
            }
#pragma unroll
            for (int nf = 0; nf < 4; nf++) {
                int nc = n0w + nf * 8 + gid;
                uint32_t b0 = Bs[(ks + tig) * BSTR + nc];
                uint32_t b1 = Bs[(ks + tig + 4) * BSTR + nc];
#pragma unroll
                for (int mf = 0; mf < 2; mf++)
                    mma_tf32(acc[mf][nf][0], acc[mf][nf][1],
                             acc[mf][nf][2], acc[mf][nf][3],
                             a[mf][0], a[mf][1], a[mf][2], a[mf][3], b0, b1);
            }
        }
    }

    const float* bb = bias + (size_t)e * DM_ + n0;
#pragma unroll
    for (int mf = 0; mf < 2; mf++) {
        int rbase = m0w + mf * 16 + gid;
#pragma unroll
        for (int half = 0; half < 2; half++) {
            int r = rbase + half * 8;
            int tok = stok[r];
            if (tok < 0) continue;
            float w = sw[r];
            float* op = out + (size_t)tok * DM_ + n0;
#pragma unroll
            for (int nf = 0; nf < 4; nf++) {
                int cc = n0w + nf * 8 + tig * 2;
                atomicAdd(op + cc,     w * (acc[mf][nf][half*2+0] + bb[cc]));
                atomicAdd(op + cc + 1, w * (acc[mf][nf][half*2+1] + bb[cc+1]));
            }
        }
    }
}

// ---------------- launch -----------------------------------------------------
extern "C" void kernel_launch(void* const* d_in, const int* in_sizes, int n_in,
                              void* d_out, int out_size) {
    const float* x  = (const float*)d_in[0];
    const float* Wg = (const float*)d_in[1];
    const float* W1 = (const float*)d_in[2];
    const float* b1 = (const float*)d_in[3];
    const float* W2 = (const float*)d_in[4];
    const float* b2 = (const float*)d_in[5];
    float* out = (float*)d_out;

    k_reset<<<256, 256>>>(out, out_size);
    k_gate<<<(NS * 32 + 255) / 256, 256>>>(x, Wg);
    k_scan<<<1, 256>>>();
    k_scatter<<<(SLOTS + 255) / 256, 256>>>();
    k_ffn1<<<dim3(MAXT,  DF_ / 128), 256>>>(x, W1, b1);
    k_ffn2<<<dim3(MAXT2, DM_ / 128), 256>>>(W2, b2, out);
}

// round 14
// speedup vs baseline: 2.2290x; 1.0201x over previous
#include <cuda_runtime.h>
#include <cstdint>
#include <math.h>

// ---------------- problem constants -----------------------------------------
#define NS   4096
#define DM_  768
#define DF_  3072
#define NE   8
#define TOPK 2
#define SLOTS (NS*TOPK)
#define TM   128
#define CAP  (SLOTS + NE*TM)    // 9216 padded rows
#define MAXT (CAP/TM)           // 72
#define TM2  64
#define MAXT2 (CAP/TM2)         // 144

#define ASTR 36                 // A smem row stride (floats)
#define BSTR 136                // B smem row stride (floats)

// dynamic smem layout (double-buffered)
#define ASZ1 (128*ASTR*4)       // 18432 B
#define ASZ2 (TM2*ASTR*4)       // 9216 B
#define BSZ  (32*BSTR*4)        // 17408 B
#define DSM1 (2*ASZ1 + 2*BSZ)   // 71680 B
#define DSM2 (2*ASZ2 + 2*BSZ)   // 53248 B

// ---------------- device scratch (no allocations allowed) -------------------
__device__ int   g_cur[NE];
__device__ int   g_eid[SLOTS];
__device__ float g_gw [SLOTS];
__device__ int   g_row_tok[CAP];
__device__ float g_row_w [CAP];
__device__ int   g_tile_e  [MAXT];
__device__ int   g_tile_row[MAXT];
__device__ int   g_ntiles;
__device__ int   g_tile2_e  [MAXT2];
__device__ int   g_tile2_row[MAXT2];
__device__ int   g_ntiles2;
__device__ float g_H[(size_t)CAP * DF_];   // 113 MB fp32 intermediate

// ---------------- helpers -----------------------------------------------------
__device__ __forceinline__ uint32_t f2tf32(float x) {
    uint32_t r; asm("cvt.rna.tf32.f32 %0, %1;" : "=r"(r) : "f"(x)); return r;
}

__device__ __forceinline__ void mma_tf32(float& c0, float& c1, float& c2, float& c3,
                                         uint32_t a0, uint32_t a1, uint32_t a2, uint32_t a3,
                                         uint32_t b0, uint32_t b1) {
    asm volatile(
        "mma.sync.aligned.m16n8k8.row.col.f32.tf32.tf32.f32 "
        "{%0,%1,%2,%3}, {%4,%5,%6,%7}, {%8,%9}, {%0,%1,%2,%3};"
        : "+f"(c0), "+f"(c1), "+f"(c2), "+f"(c3)
        : "r"(a0), "r"(a1), "r"(a2), "r"(a3), "r"(b0), "r"(b1));
}

__device__ __forceinline__ uint4 cvt4(float4 v) {
    uint4 u;
    u.x = f2tf32(v.x); u.y = f2tf32(v.y); u.z = f2tf32(v.z); u.w = f2tf32(v.w);
    return u;
}

// ---------------- 1: gating (one warp per token, pure fp32; no atomics) ------
__global__ void k_gate(const float* __restrict__ x, const float* __restrict__ Wg) {
    int warp = (blockIdx.x * blockDim.x + threadIdx.x) >> 5;
    int lane = threadIdx.x & 31;
    if (warp >= NS) return;
    const float* xs = x + (size_t)warp * DM_;
    float acc[NE];
#pragma unroll
    for (int e = 0; e < NE; e++) acc[e] = 0.f;
    for (int i = lane; i < DM_; i += 32) {
        float xv = xs[i];
#pragma unroll
        for (int e = 0; e < NE; e++) acc[e] += xv * Wg[i * NE + e];
    }
#pragma unroll
    for (int e = 0; e < NE; e++)
#pragma unroll
        for (int o = 16; o > 0; o >>= 1)
            acc[e] += __shfl_xor_sync(0xffffffffu, acc[e], o);
    if (lane == 0) {
        int e0 = 0;
#pragma unroll
        for (int e = 1; e < NE; e++) if (acc[e] > acc[e0]) e0 = e;
        int e1 = (e0 == 0) ? 1 : 0;
#pragma unroll
        for (int e = 0; e < NE; e++)
            if (e != e0 && acc[e] > acc[e1]) e1 = e;
        float w1 = 1.f / (1.f + expf(acc[e0] - acc[e1]));
        float w0 = 1.f - w1;
        g_eid[warp]      = e0;  g_gw[warp]      = w0;
        g_eid[NS + warp] = e1;  g_gw[NS + warp] = w1;
    }
}

// ---------------- 2: scan: zero out, histogram g_eid, build tile tables ------
__global__ void k_scan(float* __restrict__ out, int n) {
    int gtid = blockIdx.x * blockDim.x + threadIdx.x;
    for (int j = gtid; j < n; j += gridDim.x * blockDim.x) out[j] = 0.f;

    if (blockIdx.x == 1) {                     // init grouped-row arrays
        for (int i = threadIdx.x; i < CAP; i += blockDim.x) {
            g_row_tok[i] = -1; g_row_w[i] = 0.f;
        }
    }
    if (blockIdx.x == 0) {
        __shared__ int hcnt[NE];
        int t = threadIdx.x;
        if (t < NE) hcnt[t] = 0;
        __syncthreads();
        for (int i = t; i < SLOTS; i += blockDim.x)
            atomicAdd(&hcnt[g_eid[i]], 1);
        __syncthreads();
        if (t == 0) {
            int off = 0, nt = 0, nt2 = 0;
            for (int e = 0; e < NE; e++) {
                g_cur[e] = off;
                int cnt = hcnt[e];
                int tiles = (cnt + TM - 1) / TM;
                for (int k = 0; k < tiles; k++) {
                    g_tile_e[nt] = e; g_tile_row[nt] = off + k * TM; nt++;
                }
                int tiles2 = (cnt + TM2 - 1) / TM2;
                for (int k = 0; k < tiles2; k++) {
                    g_tile2_e[nt2] = e; g_tile2_row[nt2] = off + k * TM2; nt2++;
                }
                off += tiles * TM;
            }
            g_ntiles = nt;
            g_ntiles2 = nt2;
        }
    }
}

// ---------------- 3: scatter --------------------------------------------------
__global__ void k_scatter() {
    int i = blockIdx.x * blockDim.x + threadIdx.x;
    if (i >= SLOTS) return;
    int e = g_eid[i];
    int pos = atomicAdd(&g_cur[e], 1);
    g_row_tok[pos] = i % NS;
    g_row_w[pos]   = g_gw[i];
}

// ---------------- 4: FFN1  H = relu(Xg @ W1[e] + b1[e]) ----------------------
// Tile 128m x 128n x k32, double-buffered smem, ONE sync per chunk.
// Grid (NB, NT): same-tile n-replicas adjacent -> A-tile L2 reuse.
__global__ void __launch_bounds__(256, 2) k_ffn1(
    const float* __restrict__ x, const float* __restrict__ W1,
    const float* __restrict__ bias)
{
    int t = blockIdx.y;
    if (t >= g_ntiles) return;
    extern __shared__ char dsm[];
    __shared__ int stok[TM];

    int e    = g_tile_e[t];
    int row0 = g_tile_row[t];
    int n0   = blockIdx.x * 128;
    int tid  = threadIdx.x;
    int wid  = tid >> 5, lane = tid & 31;
    int gid  = lane >> 2, tig = lane & 3;
    int wm   = wid >> 1,  wn  = wid & 1;
    int m0w  = wm * 32,   n0w = wn * 64;

    if (tid < TM) stok[tid] = g_row_tok[row0 + tid];
    __syncthreads();

    const float* W = W1 + (size_t)e * DM_ * DF_;

    int arow = tid >> 1, ahalf = tid & 1;          // A: 128 rows x 2 halves(16f)
    int brow = tid >> 3, bseg  = tid & 7;          // B: 32 rows x 8 segs(16f)
    const float* aptr = nullptr;
    {
        int tok = stok[arow];
        if (tok >= 0) aptr = x + (size_t)tok * DM_ + ahalf * 16;
    }
    const float* bptr = W + (size_t)brow * DF_ + n0 + bseg * 16;

    float acc[2][8][4];
#pragma unroll
    for (int mf = 0; mf < 2; mf++)
#pragma unroll
        for (int nf = 0; nf < 8; nf++)
#pragma unroll
            for (int q = 0; q < 4; q++) acc[mf][nf][q] = 0.f;

    const int NC = DM_ / 32;
    float4 fa[4], fb[4];

    // preload chunk 0, store to buf0
#pragma unroll
    for (int q = 0; q < 4; q++)
        fa[q] = aptr ? *(const float4*)(aptr + q * 4) : make_float4(0.f,0.f,0.f,0.f);
#pragma unroll
    for (int q = 0; q < 4; q++)
        fb[q] = *(const float4*)(bptr + q * 4);
    {
        uint32_t* As0 = (uint32_t*)(dsm);
        uint32_t* Bs0 = (uint32_t*)(dsm + 2*ASZ1);
#pragma unroll
        for (int q = 0; q < 4; q++)
            *(uint4*)&As0[arow * ASTR + ahalf * 16 + q * 4] = cvt4(fa[q]);
#pragma unroll
        for (int q = 0; q < 4; q++)
            *(uint4*)&Bs0[brow * BSTR + bseg * 16 + q * 4] = cvt4(fb[q]);
    }
    // prefetch chunk 1
    if (NC > 1) {
#pragma unroll
        for (int q = 0; q < 4; q++)
            fa[q] = aptr ? *(const float4*)(aptr + 32 + q * 4) : make_float4(0.f,0.f,0.f,0.f);
#pragma unroll
        for (int q = 0; q < 4; q++)
            fb[q] = *(const float4*)(bptr + (size_t)32 * DF_ + q * 4);
    }
    __syncthreads();

    for (int c = 0; c < NC; c++) {
        int buf = c & 1, nbuf = buf ^ 1;
        uint32_t* Asb = (uint32_t*)(dsm + buf  * ASZ1);
        uint32_t* Asn = (uint32_t*)(dsm + nbuf * ASZ1);
        uint32_t* Bsb = (uint32_t*)(dsm + 2*ASZ1 + buf  * BSZ);
        uint32_t* Bsn = (uint32_t*)(dsm + 2*ASZ1 + nbuf * BSZ);

        // STS chunk c+1 into the other buffer (regs already loaded)
        if (c + 1 < NC) {
#pragma unroll
            for (int q = 0; q < 4; q++)
                *(uint4*)&Asn[arow * ASTR + ahalf * 16 + q * 4] = cvt4(fa[q]);
#pragma unroll
            for (int q = 0; q < 4; q++)
                *(uint4*)&Bsn[brow * BSTR + bseg * 16 + q * 4] = cvt4(fb[q]);
        }
        // LDG chunk c+2 (hidden under MMA block)
        if (c + 2 < NC) {
            int k0n = (c + 2) * 32;
#pragma unroll
            for (int q = 0; q < 4; q++)
                fa[q] = aptr ? *(const float4*)(aptr + k0n + q * 4)
                             : make_float4(0.f,0.f,0.f,0.f);
#pragma unroll
            for (int q = 0; q < 4; q++)
                fb[q] = *(const float4*)(bptr + (size_t)k0n * DF_ + q * 4);
        }

        // MMA on chunk c
#pragma unroll
        for (int ks = 0; ks < 32; ks += 8) {
            uint32_t a[2][4];
#pragma unroll
            for (int mf = 0; mf < 2; mf++) {
                int mr = m0w + mf * 16 + gid;
                a[mf][0] = Asb[mr * ASTR + ks + tig];
                a[mf][1] = Asb[(mr + 8) * ASTR + ks + tig];
                a[mf][2] = Asb[mr * ASTR + ks + tig + 4];
                a[mf][3] = Asb[(mr + 8) * ASTR + ks + tig + 4];
            }
#pragma unroll
            for (int nf = 0; nf < 8; nf++) {
                int nc = n0w + nf * 8 + gid;
                uint32_t b0 = Bsb[(ks + tig) * BSTR + nc];
                uint32_t b1 = Bsb[(ks + tig + 4) * BSTR + nc];
#pragma unroll
                for (int mf = 0; mf < 2; mf++)
                    mma_tf32(acc[mf][nf][0], acc[mf][nf][1],
                             acc[mf][nf][2], acc[mf][nf][3],
                             a[mf][0], a[mf][1], a[mf][2], a[mf][3], b0, b1);
            }
        }
        __syncthreads();   // STS(c+1) visible; LDS(c) drained before overwrite
    }

    const float* bb = bias + (size_t)e * DF_ + n0;
#pragma unroll
    for (int mf = 0; mf < 2; mf++) {
        int rbase = m0w + mf * 16 + gid;
#pragma unroll
        for (int half = 0; half < 2; half++) {
            int r = rbase + half * 8;
            float* hp = g_H + (size_t)(row0 + r) * DF_ + n0;
#pragma unroll
            for (int nf = 0; nf < 8; nf++) {
                int cc = wn * 64 + nf * 8 + tig * 2;
                float2 v;
                v.x = fmaxf(acc[mf][nf][half*2+0] + bb[cc],     0.f);
                v.y = fmaxf(acc[mf][nf][half*2+1] + bb[cc + 1], 0.f);
                *(float2*)(hp + cc) = v;
            }
        }
    }
}

// ---------------- 5: FFN2  out[tok] += w * (H @ W2[e] + b2[e]) ---------------
// Tile 64m x 128n x k32, double-buffered, one sync per chunk.
__global__ void __launch_bounds__(256, 2) k_ffn2(
    const float* __restrict__ W2, const float* __restrict__ bias,
    float* __restrict__ out)
{
    int t = blockIdx.y;
    if (t >= g_ntiles2) return;
    extern __shared__ char dsm[];
    __shared__ int   stok[TM2];
    __shared__ float sw  [TM2];

    int e    = g_tile2_e[t];
    int row0 = g_tile2_row[t];
    int n0   = blockIdx.x * 128;
    int tid  = threadIdx.x;
    int wid  = tid >> 5, lane = tid & 31;
    int gid  = lane >> 2, tig = lane & 3;
    int wm   = wid >> 2,  wn  = wid & 3;     // 2m x 4n
    int m0w  = wm * 32,   n0w = wn * 32;

    if (tid < TM2) {
        stok[tid] = g_row_tok[row0 + tid];
        sw[tid]   = g_row_w [row0 + tid];
    }
    __syncthreads();

    const float* W = W2 + (size_t)e * DF_ * DM_;

    int arow = tid >> 2, aseg = tid & 3;     // A: 64 rows x 4 segs(8f)
    int brow = tid >> 3, bseg = tid & 7;     // B: 32 rows x 8 segs(16f)
    const float* aptr = g_H + (size_t)(row0 + arow) * DF_ + aseg * 8;
    const float* bptr = W + (size_t)brow * DM_ + n0 + bseg * 16;

    float acc[2][4][4];
#pragma unroll
    for (int mf = 0; mf < 2; mf++)
#pragma unroll
        for (int nf = 0; nf < 4; nf++)
#pragma unroll
            for (int q = 0; q < 4; q++) acc[mf][nf][q] = 0.f;

    const int NC = DF_ / 32;
    float4 fa[2], fb[4];

#pragma unroll
    for (int q = 0; q < 2; q++) fa[q] = *(const float4*)(aptr + q * 4);
#pragma unroll
    for (int q = 0; q < 4; q++) fb[q] = *(const float4*)(bptr + q * 4);
    {
        uint32_t* As0 = (uint32_t*)(dsm);
        uint32_t* Bs0 = (uint32_t*)(dsm + 2*ASZ2);
#pragma unroll
        for (int q = 0; q < 2; q++)
            *(uint4*)&As0[arow * ASTR + aseg * 8 + q * 4] = cvt4(fa[q]);
#pragma unroll
        for (int q = 0; q < 4; q++)
            *(uint4*)&Bs0[brow * BSTR + bseg * 16 + q * 4] = cvt4(fb[q]);
    }
    if (NC > 1) {
#pragma unroll
        for (int q = 0; q < 2; q++) fa[q] = *(const float4*)(aptr + 32 + q * 4);
#pragma unroll
        for (int q = 0; q < 4; q++) fb[q] = *(const float4*)(bptr + (size_t)32 * DM_ + q * 4);
    }
    __syncthreads();

    for (int c = 0; c < NC; c++) {
        int buf = c & 1, nbuf = buf ^ 1;
        uint32_t* Asb = (uint32_t*)(dsm + buf  * ASZ2);
        uint32_t* Asn = (uint32_t*)(dsm + nbuf * ASZ2);
        uint32_t* Bsb = (uint32_t*)(dsm + 2*ASZ2 + buf  * BSZ);
        uint32_t* Bsn = (uint32_t*)(dsm + 2*ASZ2 + nbuf * BSZ);

        if (c + 1 < NC) {
#pragma unroll
            for (int q = 0; q < 2; q++)
                *(uint4*)&Asn[arow * ASTR + aseg * 8 + q * 4] = cvt4(fa[q]);
#pragma unroll
            for (int q = 0; q < 4; q++)
                *(uint4*)&Bsn[brow * BSTR + bseg * 16 + q * 4] = cvt4(fb[q]);
        }
        if (c + 2 < NC) {
            int k0n = (c + 2) * 32;
#pragma unroll
            for (int q = 0; q < 2; q++)
                fa[q] = *(const float4*)(aptr + k0n + q * 4);
#pragma unroll
            for (int q = 0; q < 4; q++)
                fb[q] = *(const float4*)(bptr + (size_t)k0n * DM_ + q * 4);
        }

#pragma unroll
        for (int ks = 0; ks < 32; ks += 8) {
            uint32_t a[2][4];
#pragma unroll
            for (int mf = 0; mf < 2; mf++) {
                int mr = m0w + mf * 16 + gid;
                a[mf][0] = Asb[mr * ASTR + ks + tig];
                a[mf][1] = Asb[(mr + 8) * ASTR + ks + tig];
                a[mf][2] = Asb[mr * ASTR + ks + tig + 4];
                a[mf][3] = Asb[(mr + 8) * ASTR + ks + tig + 4];
            }
#pragma unroll
            for (int nf = 0; nf < 4; nf++) {
                int nc = n0w + nf * 8 + gid;
                uint32_t b0 = Bsb[(ks + tig) * BSTR + nc];
                uint32_t b1 = Bsb[(ks + tig + 4) * BSTR + nc];
#pragma unroll
                for (int mf = 0; mf < 2; mf++)
                    mma_tf32(acc[mf][nf][0], acc[mf][nf][1],
                             acc[mf][nf][2], acc[mf][nf][3],
                             a[mf][0], a[mf][1], a[mf][2], a[mf][3], b0, b1);
            }
        }
        __syncthreads();
    }

    const float* bb = bias + (size_t)e * DM_ + n0;
#pragma unroll
    for (int mf = 0; mf < 2; mf++) {
        int rbase = m0w + mf * 16 + gid;
#pragma unroll
        for (int half = 0; half < 2; half++) {
            int r = rbase + half * 8;
            int tok = stok[r];
            if (tok < 0) continue;
            float w = sw[r];
            float* op = out + (size_t)tok * DM_ + n0;
#pragma unroll
            for (int nf = 0; nf < 4; nf++) {
                int cc = n0w + nf * 8 + tig * 2;
                atomicAdd(op + cc,     w * (acc[mf][nf][half*2+0] + bb[cc]));
                atomicAdd(op + cc + 1, w * (acc[mf][nf][half*2+1] + bb[cc+1]));
            }
        }
    }
}

// ---------------- launch -----------------------------------------------------
extern "C" void kernel_launch(void* const* d_in, const int* in_sizes, int n_in,
                              void* d_out, int out_size) {
    const float* x  = (const float*)d_in[0];
    const float* Wg = (const float*)d_in[1];
    const float* W1 = (const float*)d_in[2];
    const float* b1 = (const float*)d_in[3];
    const float* W2 = (const float*)d_in[4];
    const float* b2 = (const float*)d_in[5];
    float* out = (float*)d_out;

    cudaFuncSetAttribute(k_ffn1, cudaFuncAttributeMaxDynamicSharedMemorySize, DSM1);
    cudaFuncSetAttribute(k_ffn2, cudaFuncAttributeMaxDynamicSharedMemorySize, DSM2);

    k_gate<<<(NS * 32 + 255) / 256, 256>>>(x, Wg);
    k_scan<<<64, 256>>>(out, out_size);
    k_scatter<<<(SLOTS + 255) / 256, 256>>>();
    k_ffn1<<<dim3(DF_ / 128, MAXT),  256, DSM1>>>(x, W1, b1);
    k_ffn2<<<dim3(DM_ / 128, MAXT2), 256, DSM2>>>(W2, b2, out);
}

// round 15
// speedup vs baseline: 4.1390x; 1.8569x over previous
#include <cuda_runtime.h>
#include <cuda_fp16.h>
#include <cstdint>
#include <math.h>

// ---------------- problem constants -----------------------------------------
#define NS   4096
#define DM_  768
#define DF_  3072
#define NE   8
#define TOPK 2
#define SLOTS (NS*TOPK)
#define TM   128
#define CAP  (SLOTS + NE*TM)    // 9216 padded rows
#define MAXT (CAP/TM)           // 72
#define TM2  64
#define MAXT2 (CAP/TM2)         // 144

#define ASTRH 20                // A smem row stride (half2 units)
#define BSTRH 136               // B smem row stride (half2 units)
#define HPR  (DF_/2)            // 1536 half2 per H row

// ---------------- device scratch (no allocations allowed) -------------------
__device__ int      g_cur[NE];
__device__ int      g_eid[SLOTS];
__device__ float    g_gw [SLOTS];
__device__ int      g_row_tok[CAP];
__device__ float    g_row_w [CAP];
__device__ int      g_tile_e  [MAXT];
__device__ int      g_tile_row[MAXT];
__device__ int      g_ntiles;
__device__ int      g_tile2_e  [MAXT2];
__device__ int      g_tile2_row[MAXT2];
__device__ int      g_ntiles2;
__device__ uint32_t g_Hh[(size_t)CAP * HPR];   // 56.6 MB fp16x2 intermediate

// ---------------- helpers -----------------------------------------------------
__device__ __forceinline__ uint32_t packh2(float lo, float hi) {
    __half2 h = __floats2half2_rn(lo, hi);   // lo -> low 16 bits (low k index)
    return *(uint32_t*)&h;
}

__device__ __forceinline__ void mma_f16(float& c0, float& c1, float& c2, float& c3,
                                        uint32_t a0, uint32_t a1, uint32_t a2, uint32_t a3,
                                        uint32_t b0, uint32_t b1) {
    asm volatile(
        "mma.sync.aligned.m16n8k16.row.col.f32.f16.f16.f32 "
        "{%0,%1,%2,%3}, {%4,%5,%6,%7}, {%8,%9}, {%0,%1,%2,%3};"
        : "+f"(c0), "+f"(c1), "+f"(c2), "+f"(c3)
        : "r"(a0), "r"(a1), "r"(a2), "r"(a3), "r"(b0), "r"(b1));
}

// ---------------- 1: gating (one warp per token, pure fp32) ------------------
__global__ void k_gate(const float* __restrict__ x, const float* __restrict__ Wg) {
    int warp = (blockIdx.x * blockDim.x + threadIdx.x) >> 5;
    int lane = threadIdx.x & 31;
    if (warp >= NS) return;
    const float* xs = x + (size_t)warp * DM_;
    float acc[NE];
#pragma unroll
    for (int e = 0; e < NE; e++) acc[e] = 0.f;
    for (int i = lane; i < DM_; i += 32) {
        float xv = xs[i];
#pragma unroll
        for (int e = 0; e < NE; e++) acc[e] += xv * Wg[i * NE + e];
    }
#pragma unroll
    for (int e = 0; e < NE; e++)
#pragma unroll
        for (int o = 16; o > 0; o >>= 1)
            acc[e] += __shfl_xor_sync(0xffffffffu, acc[e], o);
    if (lane == 0) {
        int e0 = 0;
#pragma unroll
        for (int e = 1; e < NE; e++) if (acc[e] > acc[e0]) e0 = e;
        int e1 = (e0 == 0) ? 1 : 0;
#pragma unroll
        for (int e = 0; e < NE; e++)
            if (e != e0 && acc[e] > acc[e1]) e1 = e;
        float w1 = 1.f / (1.f + expf(acc[e0] - acc[e1]));
        float w0 = 1.f - w1;
        g_eid[warp]      = e0;  g_gw[warp]      = w0;
        g_eid[NS + warp] = e1;  g_gw[NS + warp] = w1;
    }
}

// ---------------- 2: scan: zero out, histogram, tile tables ------------------
__global__ void k_scan(float* __restrict__ out, int n) {
    int gtid = blockIdx.x * blockDim.x + threadIdx.x;
    for (int j = gtid; j < n; j += gridDim.x * blockDim.x) out[j] = 0.f;

    if (blockIdx.x == 1) {
        for (int i = threadIdx.x; i < CAP; i += blockDim.x) {
            g_row_tok[i] = -1; g_row_w[i] = 0.f;
        }
    }
    if (blockIdx.x == 0) {
        __shared__ int hcnt[NE];
        int t = threadIdx.x;
        if (t < NE) hcnt[t] = 0;
        __syncthreads();
        for (int i = t; i < SLOTS; i += blockDim.x)
            atomicAdd(&hcnt[g_eid[i]], 1);
        __syncthreads();
        if (t == 0) {
            int off = 0, nt = 0, nt2 = 0;
            for (int e = 0; e < NE; e++) {
                g_cur[e] = off;
                int cnt = hcnt[e];
                int tiles = (cnt + TM - 1) / TM;
                for (int k = 0; k < tiles; k++) {
                    g_tile_e[nt] = e; g_tile_row[nt] = off + k * TM; nt++;
                }
                int tiles2 = (cnt + TM2 - 1) / TM2;
                for (int k = 0; k < tiles2; k++) {
                    g_tile2_e[nt2] = e; g_tile2_row[nt2] = off + k * TM2; nt2++;
                }
                off += tiles * TM;
            }
            g_ntiles = nt;
            g_ntiles2 = nt2;
        }
    }
}

// ---------------- 3: scatter --------------------------------------------------
__global__ void k_scatter() {
    int i = blockIdx.x * blockDim.x + threadIdx.x;
    if (i >= SLOTS) return;
    int e = g_eid[i];
    int pos = atomicAdd(&g_cur[e], 1);
    g_row_tok[pos] = i % NS;
    g_row_w[pos]   = g_gw[i];
}

// ---------------- 4: FFN1  Hh = fp16(relu(Xg @ W1[e] + b1[e])) ---------------
// fp16 m16n8k16 MMA.  Tile 128m x 128n x k32, double-buffered, 1 sync/chunk.
__global__ void __launch_bounds__(256, 2) k_ffn1(
    const float* __restrict__ x, const float* __restrict__ W1,
    const float* __restrict__ bias)
{
    int t = blockIdx.y;
    if (t >= g_ntiles) return;

    __shared__ uint32_t Ash[2][128 * ASTRH];   // half2 pairs [m][k/2]
    __shared__ uint32_t Bsh[2][16 * BSTRH];    // half2 pairs [k/2][n]
    __shared__ int stok[TM];

    int e    = g_tile_e[t];
    int row0 = g_tile_row[t];
    int n0   = blockIdx.x * 128;
    int tid  = threadIdx.x;
    int wid  = tid >> 5, lane = tid & 31;
    int gid  = lane >> 2, tig = lane & 3;
    int wm   = wid >> 1,  wn  = wid & 1;      // 4m x 2n warps
    int m0w  = wm * 32,   n0w = wn * 64;

    if (tid < TM) stok[tid] = g_row_tok[row0 + tid];
    __syncthreads();

    const float* W = W1 + (size_t)e * DM_ * DF_;

    // A: 128 rows x 2 halves (16 floats each)
    int arow = tid >> 1, ahalf = tid & 1;
    const float* aptr = nullptr;
    { int tok = stok[arow]; if (tok >= 0) aptr = x + (size_t)tok * DM_ + ahalf * 16; }
    // B: pair-rows: pk=tid>>4 (0..15), colgroup cg=tid&15 (8 cols each)
    int pk = tid >> 4, cg = tid & 15;
    const float* bptr = W + (size_t)(2 * pk) * DF_ + n0 + cg * 8;

    float acc[2][8][4];
#pragma unroll
    for (int mf = 0; mf < 2; mf++)
#pragma unroll
        for (int nf = 0; nf < 8; nf++)
#pragma unroll
            for (int q = 0; q < 4; q++) acc[mf][nf][q] = 0.f;

    const int NC = DM_ / 32;
    float4 fa[4], fb[4];

    // load chunk0
#pragma unroll
    for (int q = 0; q < 4; q++)
        fa[q] = aptr ? *(const float4*)(aptr + q * 4) : make_float4(0.f,0.f,0.f,0.f);
    fb[0] = *(const float4*)(bptr);
    fb[1] = *(const float4*)(bptr + 4);
    fb[2] = *(const float4*)(bptr + DF_);
    fb[3] = *(const float4*)(bptr + DF_ + 4);
    // STS chunk0 -> buf0
    {
        uint32_t ha[8];
#pragma unroll
        for (int q = 0; q < 4; q++) {
            ha[2*q]   = packh2(fa[q].x, fa[q].y);
            ha[2*q+1] = packh2(fa[q].z, fa[q].w);
        }
        *(uint4*)&Ash[0][arow * ASTRH + ahalf * 8]     = *(uint4*)&ha[0];
        *(uint4*)&Ash[0][arow * ASTRH + ahalf * 8 + 4] = *(uint4*)&ha[4];
        uint32_t hb[8];
        hb[0]=packh2(fb[0].x,fb[2].x); hb[1]=packh2(fb[0].y,fb[2].y);
        hb[2]=packh2(fb[0].z,fb[2].z); hb[3]=packh2(fb[0].w,fb[2].w);
        hb[4]=packh2(fb[1].x,fb[3].x); hb[5]=packh2(fb[1].y,fb[3].y);
        hb[6]=packh2(fb[1].z,fb[3].z); hb[7]=packh2(fb[1].w,fb[3].w);
        *(uint4*)&Bsh[0][pk * BSTRH + cg * 8]     = *(uint4*)&hb[0];
        *(uint4*)&Bsh[0][pk * BSTRH + cg * 8 + 4] = *(uint4*)&hb[4];
    }
    // prefetch chunk1
    if (NC > 1) {
#pragma unroll
        for (int q = 0; q < 4; q++)
            fa[q] = aptr ? *(const float4*)(aptr + 32 + q * 4) : make_float4(0.f,0.f,0.f,0.f);
        const float* bp = bptr + (size_t)32 * DF_;
        fb[0] = *(const float4*)(bp);
        fb[1] = *(const float4*)(bp + 4);
        fb[2] = *(const float4*)(bp + DF_);
        fb[3] = *(const float4*)(bp + DF_ + 4);
    }
    __syncthreads();

    for (int c = 0; c < NC; c++) {
        int buf = c & 1, nbuf = buf ^ 1;

        // STS chunk c+1 into other buffer
        if (c + 1 < NC) {
            uint32_t ha[8];
#pragma unroll
            for (int q = 0; q < 4; q++) {
                ha[2*q]   = packh2(fa[q].x, fa[q].y);
                ha[2*q+1] = packh2(fa[q].z, fa[q].w);
            }
            *(uint4*)&Ash[nbuf][arow * ASTRH + ahalf * 8]     = *(uint4*)&ha[0];
            *(uint4*)&Ash[nbuf][arow * ASTRH + ahalf * 8 + 4] = *(uint4*)&ha[4];
            uint32_t hb[8];
            hb[0]=packh2(fb[0].x,fb[2].x); hb[1]=packh2(fb[0].y,fb[2].y);
            hb[2]=packh2(fb[0].z,fb[2].z); hb[3]=packh2(fb[0].w,fb[2].w);
            hb[4]=packh2(fb[1].x,fb[3].x); hb[5]=packh2(fb[1].y,fb[3].y);
            hb[6]=packh2(fb[1].z,fb[3].z); hb[7]=packh2(fb[1].w,fb[3].w);
            *(uint4*)&Bsh[nbuf][pk * BSTRH + cg * 8]     = *(uint4*)&hb[0];
            *(uint4*)&Bsh[nbuf][pk * BSTRH + cg * 8 + 4] = *(uint4*)&hb[4];
        }
        // LDG chunk c+2
        if (c + 2 < NC) {
            int k0n = (c + 2) * 32;
#pragma unroll
            for (int q = 0; q < 4; q++)
                fa[q] = aptr ? *(const float4*)(aptr + k0n + q * 4)
                             : make_float4(0.f,0.f,0.f,0.f);
            const float* bp = bptr + (size_t)k0n * DF_;
            fb[0] = *(const float4*)(bp);
            fb[1] = *(const float4*)(bp + 4);
            fb[2] = *(const float4*)(bp + DF_);
            fb[3] = *(const float4*)(bp + DF_ + 4);
        }

        // MMA: 2 k16-slices (pair offsets 0, 8)
#pragma unroll
        for (int ks2 = 0; ks2 < 16; ks2 += 8) {
            uint32_t a[2][4];
#pragma unroll
            for (int mf = 0; mf < 2; mf++) {
                int mr = m0w + mf * 16 + gid;
                a[mf][0] = Ash[buf][mr * ASTRH + ks2 + tig];
                a[mf][1] = Ash[buf][(mr + 8) * ASTRH + ks2 + tig];
                a[mf][2] = Ash[buf][mr * ASTRH + ks2 + tig + 4];
                a[mf][3] = Ash[buf][(mr + 8) * ASTRH + ks2 + tig + 4];
            }
#pragma unroll
            for (int nf = 0; nf < 8; nf++) {
                int nc = n0w + nf * 8 + gid;
                uint32_t b0 = Bsh[buf][(ks2 + tig) * BSTRH + nc];
                uint32_t b1 = Bsh[buf][(ks2 + tig + 4) * BSTRH + nc];
#pragma unroll
                for (int mf = 0; mf < 2; mf++)
                    mma_f16(acc[mf][nf][0], acc[mf][nf][1],
                            acc[mf][nf][2], acc[mf][nf][3],
                            a[mf][0], a[mf][1], a[mf][2], a[mf][3], b0, b1);
            }
        }
        __syncthreads();
    }

    const float* bb = bias + (size_t)e * DF_ + n0;
#pragma unroll
    for (int mf = 0; mf < 2; mf++) {
        int rbase = m0w + mf * 16 + gid;
#pragma unroll
        for (int half = 0; half < 2; half++) {
            int r = rbase + half * 8;
            uint32_t* hp = g_Hh + (size_t)(row0 + r) * HPR + n0 / 2;
#pragma unroll
            for (int nf = 0; nf < 8; nf++) {
                int cc = wn * 64 + nf * 8 + tig * 2;   // even column
                float vx = fmaxf(acc[mf][nf][half*2+0] + bb[cc],     0.f);
                float vy = fmaxf(acc[mf][nf][half*2+1] + bb[cc + 1], 0.f);
                hp[cc / 2] = packh2(vx, vy);
            }
        }
    }
}

// ---------------- 5: FFN2  out[tok] += w * (Hh @ W2[e] + b2[e]) --------------
// Tile 64m x 128n x k32, fp16 MMA, 8 warps (2m x 4n).
__global__ void __launch_bounds__(256, 2) k_ffn2(
    const float* __restrict__ W2, const float* __restrict__ bias,
    float* __restrict__ out)
{
    int t = blockIdx.y;
    if (t >= g_ntiles2) return;

    __shared__ uint32_t Ash[2][TM2 * ASTRH];
    __shared__ uint32_t Bsh[2][16 * BSTRH];
    __shared__ int   stok[TM2];
    __shared__ float sw  [TM2];

    int e    = g_tile2_e[t];
    int row0 = g_tile2_row[t];
    int n0   = blockIdx.x * 128;
    int tid  = threadIdx.x;
    int wid  = tid >> 5, lane = tid & 31;
    int gid  = lane >> 2, tig = lane & 3;
    int wm   = wid >> 2,  wn  = wid & 3;     // 2m x 4n
    int m0w  = wm * 32,   n0w = wn * 32;

    if (tid < TM2) {
        stok[tid] = g_row_tok[row0 + tid];
        sw[tid]   = g_row_w [row0 + tid];
    }
    __syncthreads();

    const float* W = W2 + (size_t)e * DF_ * DM_;

    // A: g_Hh pairs, 64 rows x 16 pairs: arow=tid>>2, aseg=tid&3 (4 pairs each)
    int arow = tid >> 2, aseg = tid & 3;
    const uint32_t* aptr = g_Hh + (size_t)(row0 + arow) * HPR + aseg * 4;
    // B: pk=tid>>4, cg=tid&15
    int pk = tid >> 4, cg = tid & 15;
    const float* bptr = W + (size_t)(2 * pk) * DM_ + n0 + cg * 8;

    float acc[2][4][4];
#pragma unroll
    for (int mf = 0; mf < 2; mf++)
#pragma unroll
        for (int nf = 0; nf < 4; nf++)
#pragma unroll
            for (int q = 0; q < 4; q++) acc[mf][nf][q] = 0.f;

    const int NC = DF_ / 32;
    uint4 ua;
    float4 fb[4];

    ua = *(const uint4*)(aptr);
    fb[0] = *(const float4*)(bptr);
    fb[1] = *(const float4*)(bptr + 4);
    fb[2] = *(const float4*)(bptr + DM_);
    fb[3] = *(const float4*)(bptr + DM_ + 4);
    {
        *(uint4*)&Ash[0][arow * ASTRH + aseg * 4] = ua;
        uint32_t hb[8];
        hb[0]=packh2(fb[0].x,fb[2].x); hb[1]=packh2(fb[0].y,fb[2].y);
        hb[2]=packh2(fb[0].z,fb[2].z); hb[3]=packh2(fb[0].w,fb[2].w);
        hb[4]=packh2(fb[1].x,fb[3].x); hb[5]=packh2(fb[1].y,fb[3].y);
        hb[6]=packh2(fb[1].z,fb[3].z); hb[7]=packh2(fb[1].w,fb[3].w);
        *(uint4*)&Bsh[0][pk * BSTRH + cg * 8]     = *(uint4*)&hb[0];
        *(uint4*)&Bsh[0][pk * BSTRH + cg * 8 + 4] = *(uint4*)&hb[4];
    }
    if (NC > 1) {
        ua = *(const uint4*)(aptr + 16);
        const float* bp = bptr + (size_t)32 * DM_;
        fb[0] = *(const float4*)(bp);
        fb[1] = *(const float4*)(bp + 4);
        fb[2] = *(const float4*)(bp + DM_);
        fb[3] = *(const float4*)(bp + DM_ + 4);
    }
    __syncthreads();

    for (int c = 0; c < NC; c++) {
        int buf = c & 1, nbuf = buf ^ 1;

        if (c + 1 < NC) {
            *(uint4*)&Ash[nbuf][arow * ASTRH + aseg * 4] = ua;
            uint32_t hb[8];
            hb[0]=packh2(fb[0].x,fb[2].x); hb[1]=packh2(fb[0].y,fb[2].y);
            hb[2]=packh2(fb[0].z,fb[2].z); hb[3]=packh2(fb[0].w,fb[2].w);
            hb[4]=packh2(fb[1].x,fb[3].x); hb[5]=packh2(fb[1].y,fb[3].y);
            hb[6]=packh2(fb[1].z,fb[3].z); hb[7]=packh2(fb[1].w,fb[3].w);
            *(uint4*)&Bsh[nbuf][pk * BSTRH + cg * 8]     = *(uint4*)&hb[0];
            *(uint4*)&Bsh[nbuf][pk * BSTRH + cg * 8 + 4] = *(uint4*)&hb[4];
        }
        if (c + 2 < NC) {
            int k0n = (c + 2) * 32;
            ua = *(const uint4*)(aptr + k0n / 2);
            const float* bp = bptr + (size_t)k0n * DM_;
            fb[0] = *(const float4*)(bp);
            fb[1] = *(const float4*)(bp + 4);
            fb[2] = *(const float4*)(bp + DM_);
            fb[3] = *(const float4*)(bp + DM_ + 4);
        }

#pragma unroll
        for (int ks2 = 0; ks2 < 16; ks2 += 8) {
            uint32_t a[2][4];
#pragma unroll
            for (int mf = 0; mf < 2; mf++) {
                int mr = m0w + mf * 16 + gid;
                a[mf][0] = Ash[buf][mr * ASTRH + ks2 + tig];
                a[mf][1] = Ash[buf][(mr + 8) * ASTRH + ks2 + tig];
                a[mf][2] = Ash[buf][mr * ASTRH + ks2 + tig + 4];
                a[mf][3] = Ash[buf][(mr + 8) * ASTRH + ks2 + tig + 4];
            }
#pragma unroll
            for (int nf = 0; nf < 4; nf++) {
                int nc = n0w + nf * 8 + gid;
                uint32_t b0 = Bsh[buf][(ks2 + tig) * BSTRH + nc];
                uint32_t b1 = Bsh[buf][(ks2 + tig + 4) * BSTRH + nc];
#pragma unroll
                for (int mf = 0; mf < 2; mf++)
                    mma_f16(acc[mf][nf][0], acc[mf][nf][1],
                            acc[mf][nf][2], acc[mf][nf][3],
                            a[mf][0], a[mf][1], a[mf][2], a[mf][3], b0, b1);
            }
        }
        __syncthreads();
    }

    const float* bb = bias + (size_t)e * DM_ + n0;
#pragma unroll
    for (int mf = 0; mf < 2; mf++) {
        int rbase = m0w + mf * 16 + gid;
#pragma unroll
        for (int half = 0; half < 2; half++) {
            int r = rbase + half * 8;
            int tok = stok[r];
            if (tok < 0) continue;
            float w = sw[r];
            float* op = out + (size_t)tok * DM_ + n0;
#pragma unroll
            for (int nf = 0; nf < 4; nf++) {
                int cc = n0w + nf * 8 + tig * 2;
                atomicAdd(op + cc,     w * (acc[mf][nf][half*2+0] + bb[cc]));
                atomicAdd(op + cc + 1, w * (acc[mf][nf][half*2+1] + bb[cc+1]));
            }
        }
    }
}

// ---------------- launch -----------------------------------------------------
extern "C" void kernel_launch(void* const* d_in, const int* in_sizes, int n_in,
                              void* d_out, int out_size) {
    const float* x  = (const float*)d_in[0];
    const float* Wg = (const float*)d_in[1];
    const float* W1 = (const float*)d_in[2];
    const float* b1 = (const float*)d_in[3];
    const float* W2 = (const float*)d_in[4];
    const float* b2 = (const float*)d_in[5];
    float* out = (float*)d_out;

    k_gate<<<(NS * 32 + 255) / 256, 256>>>(x, Wg);
    k_scan<<<64, 256>>>(out, out_size);
    k_scatter<<<(SLOTS + 255) / 256, 256>>>();
    k_ffn1<<<dim3(DF_ / 128, MAXT),  256>>>(x, W1, b1);
    k_ffn2<<<dim3(DM_ / 128, MAXT2), 256>>>(W2, b2, out);
}